// round 13
// baseline (speedup 1.0000x reference)
#include <cuda_runtime.h>
#include <cuda_fp16.h>
#include <cstdint>

#define KC 512
#define DC 256
#define BC 32
#define TC 4096
#define BT 128
#define EPS 5e-4f

// smem layout (bytes); stride 132 (h2 or float) => rows 528B: 16B-aligned, banks spread by 4
#define OFF_ZH 0                        // half2 [128 t][132]   (67584 B)
#define OFF_ZT 67584                    // float [128 d][132] staging; aliases WH after prologue
#define OFF_WH 67584                    // half2 [64 k][132]    (33792 B live)
#define OFF_WQ 135168                   // float[512]
#define OFF_ZQS 137216                  // float[128]
#define OFF_ZFL 137728                  // char[128]
#define SMEM_BYTES 137856

__device__ __half2 g_wh[KC * 128];      // w' = 512*w as fp16 d-pairs
__device__ float g_wq[KC];
__device__ int g_cnt;
__device__ int g_list[BC * TC];

union H24 { int4 v; __half2 h[4]; };

__device__ __forceinline__ uint32_t smem_u32(const void* p) {
    uint32_t a;
    asm("{ .reg .u64 t; cvta.to.shared.u64 t, %1; cvt.u32.u64 %0, t; }" : "=r"(a) : "l"(p));
    return a;
}

// ---- prep: g_wh = fp16(512*w) pairs; exact fp32 ||w||^2; reset flag count ----
__global__ void prep_kernel(const float* __restrict__ w) {
    int k = blockIdx.x, d = threadIdx.x;          // d = pair index 0..127
    if (k == 0 && d == 0) g_cnt = 0;
    float w0 = w[k * DC + 2 * d] * 512.0f;
    float w1 = w[k * DC + 2 * d + 1] * 512.0f;
    g_wh[k * 128 + d] = __floats2half2_rn(w0, w1);
    if (d == 0) {
        const float4* wr = (const float4*)(w + (size_t)k * DC);
        float s = 0.f;
        #pragma unroll
        for (int c = 0; c < DC / 4; ++c) {
            float4 v = wr[c];
            s += v.x * v.x + v.y * v.y + v.z * v.z + v.w * v.w;
        }
        g_wq[k] = s;
    }
}

// ---- main: HFMA2 GEMM (fp16 run-accum -> fp32) + exact-rounded top-2 argmin ----
__global__ __launch_bounds__(256, 1)
void vq_h2_kernel(const float* __restrict__ z, float* __restrict__ out)
{
    extern __shared__ char smem[];
    __half2* Zh  = (__half2*)(smem + OFF_ZH);     // [t][132]
    float*   zt  = (float*)(smem + OFF_ZT);       // [d][132] fp32 staging
    __half2* Wh  = (__half2*)(smem + OFF_WH);     // [k][132]
    float*   wqs = (float*)(smem + OFF_WQ);
    float*   zqs = (float*)(smem + OFF_ZQS);
    char*    zfl = (char*)(smem + OFF_ZFL);

    const int tid = threadIdx.x, lane = tid & 31;
    const int tx = tid & 7, ty = tid >> 3;        // 8 k-lanes x 32 t-groups
    const int b = blockIdx.y, t0 = blockIdx.x * BT;
    const float4* zg4 = (const float4*)(z + (size_t)b * DC * TC + t0);

    if (tid < BT) zfl[tid] = 0;

    // ---- Prologue: stage fp32 (two d-halves) -> exact-serial z_sq -> fp16 pairs ----
    float zq = 0.f, amax = 0.f;
    for (int h = 0; h < 2; ++h) {
        if (h) __syncthreads();
        #pragma unroll 4
        for (int i = 0; i < 16; ++i) {
            int f = tid + 256 * i, d = f >> 5, c = f & 31;
            float4 v = zg4[(size_t)(h * 128 + d) * (TC / 4) + c];
            *(float4*)(zt + d * 132 + c * 4) = v;
        }
        __syncthreads();
        if (tid < BT) {
            #pragma unroll 8
            for (int d = 0; d < 128; ++d) {       // serial d-order: validated R5 semantics
                float v = zt[d * 132 + tid];
                zq = __fadd_rn(zq, __fmul_rn(v, v));
            }
        }
        {
            int t = tid & 127, dbase = (tid >> 7) * 64;   // local d range [dbase, dbase+64)
            #pragma unroll 8
            for (int m = 0; m < 32; ++m) {
                float a = zt[(dbase + 2 * m) * 132 + t];
                float c = zt[(dbase + 2 * m + 1) * 132 + t];
                amax = fmaxf(amax, fmaxf(fabsf(a), fabsf(c)));
                Zh[t * 132 + h * 64 + (dbase >> 1) + m] = __floats2half2_rn(a, c);
            }
        }
        __syncthreads();    // half h fully consumed before zt reuse / Wh alias
    }
    if (tid < BT) zqs[tid] = zq;
    if (amax > 8.0f) zfl[tid & 127] = 1;          // quantizer-range insurance
    #pragma unroll
    for (int i = 0; i < 2; ++i) wqs[tid + 256 * i] = g_wq[tid + 256 * i];
    __syncthreads();

    unsigned long long t1[4];
    float f2[4];
    #pragma unroll
    for (int i = 0; i < 4; ++i) { t1[i] = ~0ull; f2[i] = 3.402823466e38f; }

    for (int ch = 0; ch < 8; ++ch) {
        // ---- stage W chunk [64 k][128 h2] into padded rows (int4 copies) ----
        {
            const int4* src = (const int4*)(g_wh + (size_t)ch * 64 * 128);
            #pragma unroll 4
            for (int f = tid; f < 2048; f += 256) {
                int k = f >> 5, g = f & 31;
                *(int4*)&Wh[k * 132 + g * 4] = src[(size_t)k * 32 + g];
            }
        }
        __syncthreads();

        float facc[4][8];
        #pragma unroll
        for (int i = 0; i < 4; ++i)
            #pragma unroll
            for (int j = 0; j < 8; ++j) facc[i][j] = 0.f;

        #pragma unroll
        for (int run = 0; run < 4; ++run) {       // 4 runs of 64 d (32 h2) each
            __half2 hacc[4][8];
            #pragma unroll
            for (int i = 0; i < 4; ++i)
                #pragma unroll
                for (int j = 0; j < 8; ++j) hacc[i][j] = __floats2half2_rn(0.f, 0.f);

            #pragma unroll
            for (int g8 = 0; g8 < 8; ++g8) {      // 8 groups of 4 h2 (8 d) per run
                const int d2 = run * 32 + g8 * 4;
                H24 zf[4], wf[8];
                #pragma unroll
                for (int i = 0; i < 4; ++i)
                    zf[i].v = *(const int4*)&Zh[(ty + 32 * i) * 132 + d2];
                #pragma unroll
                for (int j = 0; j < 8; ++j)
                    wf[j].v = *(const int4*)&Wh[(tx + 8 * j) * 132 + d2];
                #pragma unroll
                for (int i = 0; i < 4; ++i)
                    #pragma unroll
                    for (int j = 0; j < 8; ++j) {
                        hacc[i][j] = __hfma2(zf[i].h[0], wf[j].h[0], hacc[i][j]);
                        hacc[i][j] = __hfma2(zf[i].h[1], wf[j].h[1], hacc[i][j]);
                        hacc[i][j] = __hfma2(zf[i].h[2], wf[j].h[2], hacc[i][j]);
                        hacc[i][j] = __hfma2(zf[i].h[3], wf[j].h[3], hacc[i][j]);
                    }
            }
            // flush run to fp32
            #pragma unroll
            for (int i = 0; i < 4; ++i)
                #pragma unroll
                for (int j = 0; j < 8; ++j) {
                    float2 f = __half22float2(hacc[i][j]);
                    facc[i][j] += f.x + f.y;
                }
        }

        // ---- epilogue: exact reference rounding; top1(u64) + second-best value ----
        #pragma unroll
        for (int i = 0; i < 4; ++i) {
            float zqv = zqs[ty + 32 * i];
            #pragma unroll
            for (int j = 0; j < 8; ++j) {
                int k = ch * 64 + tx + 8 * j;
                float c2 = __fmul_rn(facc[i][j], 0.00390625f);  // 2*cross = cross' * 2^-8
                float t2 = __fsub_rn(zqv, c2);
                float s  = __fadd_rn(t2, wqs[k]);
                unsigned long long cand =
                    (((unsigned long long)__float_as_uint(s)) << 32) | (uint32_t)k;
                if (cand < t1[i]) {
                    f2[i] = __uint_as_float((uint32_t)(t1[i] >> 32));
                    t1[i] = cand;
                } else {
                    f2[i] = fminf(f2[i], s);
                }
            }
        }
        __syncthreads();   // W region free for next chunk
    }

    // ---- reduce across the 8 tx lanes (xor 1,2,4), write + flag near-ties ----
    #pragma unroll
    for (int i = 0; i < 4; ++i) {
        unsigned long long v1 = t1[i];
        float vf2 = f2[i];
        #pragma unroll
        for (int off = 1; off <= 4; off <<= 1) {
            unsigned long long o1 = __shfl_xor_sync(0xffffffffu, v1, off);
            float of2 = __shfl_xor_sync(0xffffffffu, vf2, off);
            float loser;
            if (o1 < v1) { loser = __uint_as_float((uint32_t)(v1 >> 32)); v1 = o1; }
            else         { loser = __uint_as_float((uint32_t)(o1 >> 32)); }
            vf2 = fminf(fminf(vf2, of2), loser);
        }
        if ((lane & 7) == 0) {
            int row = ty + 32 * i;
            int qid = b * TC + t0 + row;
            out[qid] = (float)(unsigned int)(v1 & 0xFFFFFFFFull);
            float f1v = __uint_as_float((uint32_t)(v1 >> 32));
            if (__fsub_rn(vf2, f1v) < EPS || zfl[row]) {
                int idx = atomicAdd(&g_cnt, 1);
                g_list[idx] = qid;
            }
        }
    }
}

// ---- kernel B: exact R5-semantics re-resolve for flagged queries (validated) ----
__global__ __launch_bounds__(256, 1)
void fix_kernel(const float* __restrict__ z, const float* __restrict__ w,
                float* __restrict__ out)
{
    __shared__ float zsh[8][DC];
    const int lane = threadIdx.x & 31, wwid = threadIdx.x >> 5;
    const int wglob = blockIdx.x * 8 + wwid;
    const int nwarp = gridDim.x * 8;
    const int n = g_cnt;

    for (int i = wglob; i < n; i += nwarp) {
        int qid = g_list[i];
        int b = qid >> 12, t = qid & 4095;
        const float* zc = z + (size_t)b * DC * TC + t;
        for (int d = lane; d < DC; d += 32) zsh[wwid][d] = zc[(size_t)d * TC];
        __syncwarp();
        float zq = 0.f;
        for (int d = 0; d < DC; ++d)
            zq = __fadd_rn(zq, __fmul_rn(zsh[wwid][d], zsh[wwid][d]));

        unsigned long long best = ~0ull;
        for (int j0 = 0; j0 < 16; j0 += 4) {
            float acc[4] = {0.f, 0.f, 0.f, 0.f};
            const float* w0 = w + (size_t)(lane + 32 * (j0 + 0)) * DC;
            const float* w1p = w + (size_t)(lane + 32 * (j0 + 1)) * DC;
            const float* w2p = w + (size_t)(lane + 32 * (j0 + 2)) * DC;
            const float* w3p = w + (size_t)(lane + 32 * (j0 + 3)) * DC;
            for (int d = 0; d < DC; ++d) {
                float zv = zsh[wwid][d];
                acc[0] = __fmaf_rn(zv, w0[d], acc[0]);
                acc[1] = __fmaf_rn(zv, w1p[d], acc[1]);
                acc[2] = __fmaf_rn(zv, w2p[d], acc[2]);
                acc[3] = __fmaf_rn(zv, w3p[d], acc[3]);
            }
            #pragma unroll
            for (int u = 0; u < 4; ++u) {
                int k = lane + 32 * (j0 + u);
                float c2 = __fmul_rn(2.0f, acc[u]);
                float t2v = __fsub_rn(zq, c2);
                float s  = __fadd_rn(t2v, g_wq[k]);
                unsigned long long cand =
                    (((unsigned long long)__float_as_uint(s)) << 32) | (uint32_t)k;
                if (cand < best) best = cand;
            }
        }
        #pragma unroll
        for (int off = 16; off; off >>= 1) {
            unsigned long long o = __shfl_xor_sync(0xffffffffu, best, off);
            if (o < best) best = o;
        }
        if (lane == 0) out[qid] = (float)(unsigned int)(best & 0xFFFFFFFFull);
        __syncwarp();
    }
}

extern "C" void kernel_launch(void* const* d_in, const int* in_sizes, int n_in,
                              void* d_out, int out_size)
{
    const float* z = (const float*)d_in[0];
    const float* w = (const float*)d_in[1];
    if (n_in >= 2 && in_sizes[0] == KC * DC && in_sizes[1] == BC * DC * TC) {
        z = (const float*)d_in[1];
        w = (const float*)d_in[0];
    }
    float* out = (float*)d_out;
    (void)out_size;

    cudaFuncSetAttribute(vq_h2_kernel,
                         cudaFuncAttributeMaxDynamicSharedMemorySize, SMEM_BYTES);

    prep_kernel<<<KC, 128>>>(w);
    dim3 grid(TC / BT, BC);   // (32, 32)
    vq_h2_kernel<<<grid, 256, SMEM_BYTES>>>(z, out);
    fix_kernel<<<128, 256>>>(z, w, out);
}

// round 14
// speedup vs baseline: 3.6093x; 3.6093x over previous
#include <cuda_runtime.h>
#include <cstdint>

// Problem constants
#define KC 512
#define DC 256
#define BC 32
#define TC 4096

#define BT 128        // t rows per CTA
#define KT 32         // k per W chunk (double-buffered)
#define S  260        // row stride in floats (256 + 4)

// smem (floats): Zst 128*260=33280 | Ws 2*32*260=16640 | wq 512 | zqs 128
#define OFF_ZST 0
#define OFF_WS  33280
#define OFF_WQ  (OFF_WS + 2 * KT * S)   // 49920
#define OFF_ZQS (OFF_WQ + KC)           // 50432
#define SMEM_FLOATS 50560               // 202240 B

union F4 { float4 v; unsigned long long u[2]; };
union U2 { unsigned long long u; float f[2]; };

// Packed dual-FMA: {a0,a1}*{b0,b1} + acc elementwise (exact fp32 lanes).
__device__ __forceinline__ void ffma2(unsigned long long& acc,
                                      unsigned long long a,
                                      unsigned long long b) {
    asm("fma.rn.f32x2 %0, %1, %2, %0;" : "+l"(acc) : "l"(a), "l"(b));
}

__device__ __forceinline__ uint32_t smem_u32(const void* p) {
    uint32_t a;
    asm("{ .reg .u64 t; cvta.to.shared.u64 t, %1; cvt.u32.u64 %0, t; }" : "=r"(a) : "l"(p));
    return a;
}
__device__ __forceinline__ void cp16(uint32_t dst, const void* src) {
    asm volatile("cp.async.cg.shared.global [%0], [%1], 16;" :: "r"(dst), "l"(src));
}

__global__ __launch_bounds__(256, 1)
void vq_argmin_kernel(const float* __restrict__ z,
                      const float* __restrict__ w,
                      float* __restrict__ out)
{
    extern __shared__ float smem[];
    const uint32_t sb = smem_u32(smem);
    float* Zst  = smem + OFF_ZST;          // [t][d], stride S (d-contiguous)
    float* Ws   = smem + OFF_WS;           // 2 x [32 k][260]
    float* Ztmp = Ws;                      // [32 d][128 t] transpose staging (aliases Ws)
    float* wq   = smem + OFF_WQ;           // ||w_k||^2
    float* zqs  = smem + OFF_ZQS;          // ||z_t||^2

    const int tid = threadIdx.x;
    const int b   = blockIdx.y;
    const int t0  = blockIdx.x * BT;

    // ---- Stage Z transposed: global [d][t] -> Zst[t][d], 8 chunks of 32 d ----
    {
        const float4* zg4 = (const float4*)(z + (size_t)b * DC * TC + t0);
        const int tloc = tid & 127;
        const int g    = tid >> 7;            // 0..1
        for (int c8 = 0; c8 < 8; ++c8) {
            #pragma unroll
            for (int it = 0; it < 4; ++it) {
                int f = tid + 256 * it;       // 0..1023
                int d = f >> 5;               // 0..31
                int c = f & 31;
                float4 v = zg4[(size_t)(c8 * 32 + d) * (TC / 4) + c];
                *(float4*)&Ztmp[d * BT + c * 4] = v;
            }
            __syncthreads();
            #pragma unroll
            for (int qq = 0; qq < 4; ++qq) {
                int q = g * 4 + qq;           // 0..7 d-quad within chunk
                float4 o;
                o.x = Ztmp[(q * 4 + 0) * BT + tloc];
                o.y = Ztmp[(q * 4 + 1) * BT + tloc];
                o.z = Ztmp[(q * 4 + 2) * BT + tloc];
                o.w = Ztmp[(q * 4 + 3) * BT + tloc];
                *(float4*)&Zst[tloc * S + c8 * 32 + q * 4] = o;
            }
            __syncthreads();
        }
    }

    // ---- ||w_k||^2 (exact fp32, float4-grouped as validated) ----
    #pragma unroll
    for (int r = 0; r < 2; ++r) {
        int k = tid + 256 * r;
        const float4* wr4 = (const float4*)(w + (size_t)k * DC);
        float s = 0.f;
        #pragma unroll
        for (int c = 0; c < DC / 4; ++c) {
            float4 v = wr4[c];
            s += v.x * v.x + v.y * v.y + v.z * v.z + v.w * v.w;
        }
        wq[k] = s;
    }
    __syncthreads();

    // ---- ||z_t||^2: SERIAL in-order d, separate mul/add roundings (validated) ----
    if (tid < BT) {
        float s = 0.f;
        #pragma unroll 8
        for (int d = 0; d < DC; ++d) {
            float v = Zst[tid * S + d];
            s = __fadd_rn(s, __fmul_rn(v, v));
        }
        zqs[tid] = s;
    }
    __syncthreads();

    // ---- prefetch W chunk 0 into buffer 0 ----
    {
        #pragma unroll
        for (int it = 0; it < 8; ++it) {      // 2048 float4 / 256 thr
            int f = tid + 256 * it;
            int k = f >> 6, c = f & 63;
            cp16(sb + (uint32_t)(OFF_WS + k * S + c * 4) * 4,
                 w + (size_t)k * DC + c * 4);
        }
        asm volatile("cp.async.commit_group;" ::: "memory");
    }

    const int tx = tid & 7;   // k lane (0..7)
    const int ty = tid >> 3;  // t group (0..31), 4 t rows each

    float zq[4];
    #pragma unroll
    for (int i = 0; i < 4; ++i) zq[i] = zqs[ty * 4 + i];

    float best[4];
    int   bidx[4];
    #pragma unroll
    for (int i = 0; i < 4; ++i) { best[i] = 3.402823466e38f; bidx[i] = 0; }

    const float* zrow0 = &Zst[(ty * 4 + 0) * S];
    const float* zrow1 = &Zst[(ty * 4 + 1) * S];
    const float* zrow2 = &Zst[(ty * 4 + 2) * S];
    const float* zrow3 = &Zst[(ty * 4 + 3) * S];

    for (int ch = 0; ch < KC / KT; ++ch) {    // 16 chunks of 32 k
        const int cur = ch & 1;
        asm volatile("cp.async.wait_group 0;" ::: "memory");
        __syncthreads();                       // chunk ch ready; ch-1 compute done

        if (ch < KC / KT - 1) {               // prefetch ch+1 into other buffer
            const float* wsrc = w + (size_t)(ch + 1) * KT * DC;
            uint32_t dbase = sb + (uint32_t)(OFF_WS + (cur ^ 1) * KT * S) * 4;
            #pragma unroll
            for (int it = 0; it < 8; ++it) {
                int f = tid + 256 * it;
                int k = f >> 6, c = f & 63;
                cp16(dbase + (uint32_t)(k * S + c * 4) * 4,
                     wsrc + (size_t)k * DC + c * 4);
            }
            asm volatile("cp.async.commit_group;" ::: "memory");
        }

        const float* Wc = Ws + cur * KT * S;

        // ---- 128t x 32k x 256d sub-GEMM via f32x2 over d pairs ----
        unsigned long long acc[4][4];
        #pragma unroll
        for (int i = 0; i < 4; ++i)
            #pragma unroll
            for (int j = 0; j < 4; ++j) acc[i][j] = 0ull;

        #pragma unroll 2
        for (int d4 = 0; d4 < DC / 4; ++d4) {
            F4 zr[4];
            zr[0].v = *(const float4*)&zrow0[d4 * 4];
            zr[1].v = *(const float4*)&zrow1[d4 * 4];
            zr[2].v = *(const float4*)&zrow2[d4 * 4];
            zr[3].v = *(const float4*)&zrow3[d4 * 4];

            #pragma unroll
            for (int j = 0; j < 4; ++j) {
                F4 wr;  // k_local = tx + 8*j : 8-lane stride-260 float4, conflict-free
                wr.v = *(const float4*)&Wc[(tx + 8 * j) * S + d4 * 4];
                #pragma unroll
                for (int i = 0; i < 4; ++i) {
                    ffma2(acc[i][j], zr[i].u[0], wr.u[0]);
                    ffma2(acc[i][j], zr[i].u[1], wr.u[1]);
                }
            }
        }

        // ---- Epilogue: exact reference rounding chain; running argmin ----
        #pragma unroll
        for (int j = 0; j < 4; ++j) {
            int k = ch * KT + tx + 8 * j;     // ascending per thread
            float h = wq[k];
            #pragma unroll
            for (int i = 0; i < 4; ++i) {
                U2 u; u.u = acc[i][j];
                float cross = u.f[0] + u.f[1];
                float c2 = __fmul_rn(2.0f, cross);
                float t2 = __fsub_rn(zq[i], c2);
                float s  = __fadd_rn(t2, h);
                if (s < best[i]) { best[i] = s; bidx[i] = k; }
            }
        }
    }

    // ---- Reduce across the 8 k-lanes (width-8 xor shuffle), min + lowest idx ----
    #pragma unroll
    for (int i = 0; i < 4; ++i) {
        #pragma unroll
        for (int off = 4; off > 0; off >>= 1) {
            float ob = __shfl_xor_sync(0xffffffffu, best[i], off, 8);
            int   oi = __shfl_xor_sync(0xffffffffu, bidx[i], off, 8);
            if (ob < best[i] || (ob == best[i] && oi < bidx[i])) {
                best[i] = ob; bidx[i] = oi;
            }
        }
    }

    if (tx == 0) {
        #pragma unroll
        for (int i = 0; i < 4; ++i)
            out[(size_t)b * TC + t0 + ty * 4 + i] = (float)bidx[i];
    }
}

extern "C" void kernel_launch(void* const* d_in, const int* in_sizes, int n_in,
                              void* d_out, int out_size)
{
    const float* z = (const float*)d_in[0];
    const float* w = (const float*)d_in[1];
    if (n_in >= 2 && in_sizes[0] == KC * DC && in_sizes[1] == BC * DC * TC) {
        z = (const float*)d_in[1];
        w = (const float*)d_in[0];
    }
    float* out = (float*)d_out;
    (void)out_size;

    cudaFuncSetAttribute(vq_argmin_kernel,
                         cudaFuncAttributeMaxDynamicSharedMemorySize,
                         SMEM_FLOATS * sizeof(float));

    dim3 grid(TC / BT, BC);   // (32, 32)
    vq_argmin_kernel<<<grid, 256, SMEM_FLOATS * sizeof(float)>>>(z, w, out);
}

// round 15
// speedup vs baseline: 4.1614x; 1.1530x over previous
#include <cuda_runtime.h>
#include <cstdint>

// Problem constants
#define KC 512
#define DC 256
#define BC 32
#define TC 4096

#define BT 128        // t rows per CTA
#define KT 64         // k per smem tile
#define S  260        // row stride in floats (256 + 4; float4-aligned, banks spread by 4)

// smem (floats): Zst 128*260=33280, Ws 64*260=16640, wq 512, zqs 128  -> 50560 fl = 202240 B
// Ztmp (32*128=4096 floats) aliases the Ws region during Z staging.
#define SMEM_FLOATS (BT*S + KT*S + KC + BT)

union F4 { float4 v; unsigned long long u[2]; };
union U2 { unsigned long long u; float f[2]; };

// Packed dual-FMA: {a0,a1}*{b0,b1} + {c0,c1} elementwise, fp32 exact (2x scalar FFMA).
__device__ __forceinline__ void ffma2(unsigned long long& acc,
                                      unsigned long long a,
                                      unsigned long long b) {
    asm("fma.rn.f32x2 %0, %1, %2, %0;" : "+l"(acc) : "l"(a), "l"(b));
}

__global__ __launch_bounds__(256, 1)
void vq_argmin_kernel(const float* __restrict__ z,
                      const float* __restrict__ w,
                      float* __restrict__ out)
{
    extern __shared__ float smem[];
    float* Zst = smem;                 // [t][d], stride S (d-contiguous)
    float* Ws  = Zst + BT * S;         // [k][d], stride S (d-contiguous)
    float* Ztmp = Ws;                  // [32 d][128 t], aliases Ws during Z staging
    float* wq  = Ws + KT * S;          // ||w_k||^2, [512]
    float* zqs = wq + KC;              // ||z_t||^2, [128]

    const int tid = threadIdx.x;
    const int b   = blockIdx.y;
    const int t0  = blockIdx.x * BT;

    // ---- Stage Z transposed: global [d][t] -> Zst[t][d], via 8 chunks of 32 d ----
    {
        const float4* zg4 = (const float4*)(z + (size_t)b * DC * TC + t0);
        const int tloc = tid & 127;
        const int g    = tid >> 7;            // 0..1
        for (int c8 = 0; c8 < 8; ++c8) {
            // coalesced load chunk [32 d][128 t] into Ztmp
            #pragma unroll
            for (int it = 0; it < 4; ++it) {
                int f = tid + 256 * it;       // 0..1023
                int d = f >> 5;               // 0..31
                int c = f & 31;               // float4 col over t
                float4 v = zg4[(size_t)(c8 * 32 + d) * (TC / 4) + c];
                *(float4*)&Ztmp[d * BT + c * 4] = v;
            }
            __syncthreads();
            // transpose chunk into Zst[t][c8*32 ..]
            #pragma unroll
            for (int qq = 0; qq < 4; ++qq) {
                int q = g * 4 + qq;           // 0..7 -> d-quad within chunk
                float4 o;
                o.x = Ztmp[(q * 4 + 0) * BT + tloc];
                o.y = Ztmp[(q * 4 + 1) * BT + tloc];
                o.z = Ztmp[(q * 4 + 2) * BT + tloc];
                o.w = Ztmp[(q * 4 + 3) * BT + tloc];
                *(float4*)&Zst[tloc * S + c8 * 32 + q * 4] = o;
            }
            __syncthreads();
        }
    }

    // ---- ||w_k||^2 for all 512 k (exact fp32) ----
    #pragma unroll
    for (int r = 0; r < 2; ++r) {
        int k = tid + 256 * r;
        const float4* wr = (const float4*)(w + (size_t)k * DC);
        float s = 0.f;
        #pragma unroll
        for (int c = 0; c < DC / 4; ++c) {
            float4 v = wr[c];
            s += v.x * v.x + v.y * v.y + v.z * v.z + v.w * v.w;
        }
        wq[k] = s;
    }
    __syncthreads();

    // ---- ||z_t||^2: SERIAL in-order over d, separate mul/add roundings.
    //      Bit-identical to the validated R5 computation. ----
    if (tid < BT) {
        float s = 0.f;
        #pragma unroll 8
        for (int d = 0; d < DC; ++d) {
            float v = Zst[tid * S + d];
            s = __fadd_rn(s, __fmul_rn(v, v));
        }
        zqs[tid] = s;
    }
    __syncthreads();

    const int tx = tid & 7;   // k lane (0..7)
    const int ty = tid >> 3;  // t group (0..31), each owns 4 t rows

    float zq[4];
    #pragma unroll
    for (int i = 0; i < 4; ++i) zq[i] = zqs[ty * 4 + i];

    float best[4];
    int   bidx[4];
    #pragma unroll
    for (int i = 0; i < 4; ++i) { best[i] = 3.402823466e38f; bidx[i] = 0; }

    const float* zrow0 = &Zst[(ty * 4 + 0) * S];
    const float* zrow1 = &Zst[(ty * 4 + 1) * S];
    const float* zrow2 = &Zst[(ty * 4 + 2) * S];
    const float* zrow3 = &Zst[(ty * 4 + 3) * S];

    for (int kt = 0; kt < KC / KT; ++kt) {
        // ---- Stage W tile [64 k][256 d] (coalesced, d-contiguous rows) ----
        {
            const float4* wg = (const float4*)(w + (size_t)(kt * KT) * DC);
            #pragma unroll
            for (int i = 0; i < (KT * DC / 4) / 256; ++i) {   // 16 iters
                int f = tid + 256 * i;
                int k = f >> 6;     // f / 64
                int c = f & 63;
                float4 v = wg[(size_t)k * (DC / 4) + c];
                *(float4*)&Ws[k * S + c * 4] = v;
            }
        }
        __syncthreads();

        // ---- 128t x 64k x 256d sub-GEMM via packed f32x2 over the d dim ----
        unsigned long long acc[4][8];
        #pragma unroll
        for (int i = 0; i < 4; ++i)
            #pragma unroll
            for (int j = 0; j < 8; ++j) acc[i][j] = 0ull;

        #pragma unroll 2
        for (int d4 = 0; d4 < DC / 4; ++d4) {
            F4 zr[4];
            zr[0].v = *(const float4*)&zrow0[d4 * 4];
            zr[1].v = *(const float4*)&zrow1[d4 * 4];
            zr[2].v = *(const float4*)&zrow2[d4 * 4];
            zr[3].v = *(const float4*)&zrow3[d4 * 4];

            #pragma unroll
            for (int j = 0; j < 8; ++j) {
                F4 wr;
                wr.v = *(const float4*)&Ws[(tx + 8 * j) * S + d4 * 4];
                #pragma unroll
                for (int i = 0; i < 4; ++i) {
                    ffma2(acc[i][j], zr[i].u[0], wr.u[0]);
                    ffma2(acc[i][j], zr[i].u[1], wr.u[1]);
                }
            }
        }

        // ---- Epilogue: cross = lo+hi; exact reference rounding sequence;
        //      running argmin with first-index tie-break ----
        #pragma unroll
        for (int j = 0; j < 8; ++j) {
            int k = kt * KT + tx + 8 * j;
            float h = wq[k];
            #pragma unroll
            for (int i = 0; i < 4; ++i) {
                U2 u; u.u = acc[i][j];
                float cross = u.f[0] + u.f[1];
                float c2 = __fmul_rn(2.0f, cross);
                float t2 = __fsub_rn(zq[i], c2);
                float s  = __fadd_rn(t2, h);
                if (s < best[i]) { best[i] = s; bidx[i] = k; }
            }
        }
        __syncthreads();  // before overwriting Ws
    }

    // ---- Reduce across the 8 k-lanes (width-8 xor shuffle), min + lowest idx ----
    #pragma unroll
    for (int i = 0; i < 4; ++i) {
        #pragma unroll
        for (int off = 4; off > 0; off >>= 1) {
            float ob = __shfl_xor_sync(0xffffffffu, best[i], off, 8);
            int   oi = __shfl_xor_sync(0xffffffffu, bidx[i], off, 8);
            if (ob < best[i] || (ob == best[i] && oi < bidx[i])) {
                best[i] = ob; bidx[i] = oi;
            }
        }
    }

    if (tx == 0) {
        #pragma unroll
        for (int i = 0; i < 4; ++i)
            out[(size_t)b * TC + t0 + ty * 4 + i] = (float)bidx[i];
    }
}

extern "C" void kernel_launch(void* const* d_in, const int* in_sizes, int n_in,
                              void* d_out, int out_size)
{
    // Identify inputs by size: z_e_x has B*D*T = 33,554,432 elems,
    // emb_weight has K*D = 131,072 elems.
    const float* z = (const float*)d_in[0];
    const float* w = (const float*)d_in[1];
    if (n_in >= 2 && in_sizes[0] == KC * DC && in_sizes[1] == BC * DC * TC) {
        z = (const float*)d_in[1];
        w = (const float*)d_in[0];
    }
    float* out = (float*)d_out;               // [B, T], argmin indices as float32

    (void)out_size;

    cudaFuncSetAttribute(vq_argmin_kernel,
                         cudaFuncAttributeMaxDynamicSharedMemorySize,
                         SMEM_FLOATS * sizeof(float));

    dim3 grid(TC / BT, BC);   // (32, 32)
    vq_argmin_kernel<<<grid, 256, SMEM_FLOATS * sizeof(float)>>>(z, w, out);
}

// round 16
// speedup vs baseline: 4.8830x; 1.1734x over previous
#include <cuda_runtime.h>
#include <cstdint>

// Problem constants
#define KC 512
#define DC 256
#define BC 32
#define TC 4096

#define BT 128        // t rows per CTA
#define KT 64         // k per smem tile
#define S  260        // row stride in floats (256 + 4; float4-aligned, banks spread by 4)

// smem (floats): Zst 128*260=33280, Ws 64*260=16640, wq 512, zqs 128  -> 50560 fl = 202240 B
// Ztmp (32*128=4096 floats) aliases the Ws region during Z staging.
#define SMEM_FLOATS (BT*S + KT*S + KC + BT)

union F4 { float4 v; unsigned long long u[2]; };
union U2 { unsigned long long u; float f[2]; };

// Packed dual-FMA: {a0,a1}*{b0,b1} + {c0,c1} elementwise, fp32 exact (2x scalar FFMA).
__device__ __forceinline__ void ffma2(unsigned long long& acc,
                                      unsigned long long a,
                                      unsigned long long b) {
    asm("fma.rn.f32x2 %0, %1, %2, %0;" : "+l"(acc) : "l"(a), "l"(b));
}

// Precomputed ||w_k||^2 (written once by prep_kernel; bit-identical expression
// to the validated in-kernel computation of R5/R6).
__device__ float g_wq[KC];

__global__ void prep_kernel(const float* __restrict__ w) {
    int k = blockIdx.x * blockDim.x + threadIdx.x;   // 0..511
    const float4* wr = (const float4*)(w + (size_t)k * DC);
    float s = 0.f;
    #pragma unroll
    for (int c = 0; c < DC / 4; ++c) {
        float4 v = wr[c];
        s += v.x * v.x + v.y * v.y + v.z * v.z + v.w * v.w;
    }
    g_wq[k] = s;
}

__global__ __launch_bounds__(256, 1)
void vq_argmin_kernel(const float* __restrict__ z,
                      const float* __restrict__ w,
                      float* __restrict__ out)
{
    extern __shared__ float smem[];
    float* Zst = smem;                 // [t][d], stride S (d-contiguous)
    float* Ws  = Zst + BT * S;         // [k][d], stride S (d-contiguous)
    float* Ztmp = Ws;                  // [32 d][128 t], aliases Ws during Z staging
    float* wq  = Ws + KT * S;          // ||w_k||^2, [512]
    float* zqs = wq + KC;              // ||z_t||^2, [128]

    const int tid = threadIdx.x;
    const int b   = blockIdx.y;
    const int t0  = blockIdx.x * BT;

    // ---- wq from prep kernel (2 scalar loads/thread; replaces per-CTA recompute) ----
    wq[tid]       = g_wq[tid];
    wq[tid + 256] = g_wq[tid + 256];

    // ---- Stage Z transposed: global [d][t] -> Zst[t][d], via 8 chunks of 32 d ----
    {
        const float4* zg4 = (const float4*)(z + (size_t)b * DC * TC + t0);
        const int tloc = tid & 127;
        const int g    = tid >> 7;            // 0..1
        for (int c8 = 0; c8 < 8; ++c8) {
            // coalesced load chunk [32 d][128 t] into Ztmp
            #pragma unroll
            for (int it = 0; it < 4; ++it) {
                int f = tid + 256 * it;       // 0..1023
                int d = f >> 5;               // 0..31
                int c = f & 31;               // float4 col over t
                float4 v = zg4[(size_t)(c8 * 32 + d) * (TC / 4) + c];
                *(float4*)&Ztmp[d * BT + c * 4] = v;
            }
            __syncthreads();
            // transpose chunk into Zst[t][c8*32 ..]
            #pragma unroll
            for (int qq = 0; qq < 4; ++qq) {
                int q = g * 4 + qq;           // 0..7 -> d-quad within chunk
                float4 o;
                o.x = Ztmp[(q * 4 + 0) * BT + tloc];
                o.y = Ztmp[(q * 4 + 1) * BT + tloc];
                o.z = Ztmp[(q * 4 + 2) * BT + tloc];
                o.w = Ztmp[(q * 4 + 3) * BT + tloc];
                *(float4*)&Zst[tloc * S + c8 * 32 + q * 4] = o;
            }
            __syncthreads();
        }
    }

    // ---- ||z_t||^2: SERIAL in-order over d, separate mul/add roundings.
    //      Bit-identical to the validated R5 computation. ----
    if (tid < BT) {
        float s = 0.f;
        #pragma unroll 8
        for (int d = 0; d < DC; ++d) {
            float v = Zst[tid * S + d];
            s = __fadd_rn(s, __fmul_rn(v, v));
        }
        zqs[tid] = s;
    }
    __syncthreads();

    const int tx = tid & 7;   // k lane (0..7)
    const int ty = tid >> 3;  // t group (0..31), each owns 4 t rows

    float zq[4];
    #pragma unroll
    for (int i = 0; i < 4; ++i) zq[i] = zqs[ty * 4 + i];

    float best[4];
    int   bidx[4];
    #pragma unroll
    for (int i = 0; i < 4; ++i) { best[i] = 3.402823466e38f; bidx[i] = 0; }

    const float* zrow0 = &Zst[(ty * 4 + 0) * S];
    const float* zrow1 = &Zst[(ty * 4 + 1) * S];
    const float* zrow2 = &Zst[(ty * 4 + 2) * S];
    const float* zrow3 = &Zst[(ty * 4 + 3) * S];

    for (int kt = 0; kt < KC / KT; ++kt) {
        // ---- Stage W tile [64 k][256 d] (coalesced, d-contiguous rows) ----
        {
            const float4* wg = (const float4*)(w + (size_t)(kt * KT) * DC);
            #pragma unroll
            for (int i = 0; i < (KT * DC / 4) / 256; ++i) {   // 16 iters
                int f = tid + 256 * i;
                int k = f >> 6;     // f / 64
                int c = f & 63;
                float4 v = wg[(size_t)k * (DC / 4) + c];
                *(float4*)&Ws[k * S + c * 4] = v;
            }
        }
        __syncthreads();

        // ---- 128t x 64k x 256d sub-GEMM via packed f32x2 over the d dim ----
        unsigned long long acc[4][8];
        #pragma unroll
        for (int i = 0; i < 4; ++i)
            #pragma unroll
            for (int j = 0; j < 8; ++j) acc[i][j] = 0ull;

        #pragma unroll 2
        for (int d4 = 0; d4 < DC / 4; ++d4) {
            F4 zr[4];
            zr[0].v = *(const float4*)&zrow0[d4 * 4];
            zr[1].v = *(const float4*)&zrow1[d4 * 4];
            zr[2].v = *(const float4*)&zrow2[d4 * 4];
            zr[3].v = *(const float4*)&zrow3[d4 * 4];

            #pragma unroll
            for (int j = 0; j < 8; ++j) {
                F4 wr;
                wr.v = *(const float4*)&Ws[(tx + 8 * j) * S + d4 * 4];
                #pragma unroll
                for (int i = 0; i < 4; ++i) {
                    ffma2(acc[i][j], zr[i].u[0], wr.u[0]);
                    ffma2(acc[i][j], zr[i].u[1], wr.u[1]);
                }
            }
        }

        // ---- Epilogue: cross = lo+hi; exact reference rounding sequence;
        //      running argmin with first-index tie-break ----
        #pragma unroll
        for (int j = 0; j < 8; ++j) {
            int k = kt * KT + tx + 8 * j;
            float h = wq[k];
            #pragma unroll
            for (int i = 0; i < 4; ++i) {
                U2 u; u.u = acc[i][j];
                float cross = u.f[0] + u.f[1];
                float c2 = __fmul_rn(2.0f, cross);
                float t2 = __fsub_rn(zq[i], c2);
                float s  = __fadd_rn(t2, h);
                if (s < best[i]) { best[i] = s; bidx[i] = k; }
            }
        }
        __syncthreads();  // before overwriting Ws
    }

    // ---- Reduce across the 8 k-lanes (width-8 xor shuffle), min + lowest idx ----
    #pragma unroll
    for (int i = 0; i < 4; ++i) {
        #pragma unroll
        for (int off = 4; off > 0; off >>= 1) {
            float ob = __shfl_xor_sync(0xffffffffu, best[i], off, 8);
            int   oi = __shfl_xor_sync(0xffffffffu, bidx[i], off, 8);
            if (ob < best[i] || (ob == best[i] && oi < bidx[i])) {
                best[i] = ob; bidx[i] = oi;
            }
        }
    }

    if (tx == 0) {
        #pragma unroll
        for (int i = 0; i < 4; ++i)
            out[(size_t)b * TC + t0 + ty * 4 + i] = (float)bidx[i];
    }
}

extern "C" void kernel_launch(void* const* d_in, const int* in_sizes, int n_in,
                              void* d_out, int out_size)
{
    // Identify inputs by size: z_e_x has B*D*T = 33,554,432 elems,
    // emb_weight has K*D = 131,072 elems.
    const float* z = (const float*)d_in[0];
    const float* w = (const float*)d_in[1];
    if (n_in >= 2 && in_sizes[0] == KC * DC && in_sizes[1] == BC * DC * TC) {
        z = (const float*)d_in[1];
        w = (const float*)d_in[0];
    }
    float* out = (float*)d_out;               // [B, T], argmin indices as float32

    (void)out_size;

    cudaFuncSetAttribute(vq_argmin_kernel,
                         cudaFuncAttributeMaxDynamicSharedMemorySize,
                         SMEM_FLOATS * sizeof(float));

    prep_kernel<<<2, 256>>>(w);
    dim3 grid(TC / BT, BC);   // (32, 32)
    vq_argmin_kernel<<<grid, 256, SMEM_FLOATS * sizeof(float)>>>(z, w, out);
}